// round 16
// baseline (speedup 1.0000x reference)
#include <cuda_runtime.h>
#include <cuda_fp16.h>

// ---------------------------------------------------------------------------
// GCN: 3x (GEMM -> GCN-normalized aggregate w/ self loops -> BN(eval)+ReLU)
//      -> global mean+max pool per graph -> 2-layer MLP head.
// R14 skeleton (258.5us). This round (aggregates are ISSUE-bound, proven by
// fusion being neutral): warp-level LDG per edge cut 2 -> 0.75 via
//  (a) int4 csr loads (sequential, head-aligned),
//  (b) 16-lanes-per-row: one warp LDG.64 fetches TWO fp16 rows (half=lane>>4
//      selects edge, fl=lane&15 owns 4 features); metadata stays warp-uniform,
//  (c) depth-2 HADD2 tree before fp32 accumulate (4x fewer cvt/add).
// Merge via 4x shfl_xor(16) per node. GEMM cores / setup / MLP unchanged.
// ---------------------------------------------------------------------------

#define NN   100000
#define EE   1600000
#define GG   512
#define INF  26
#define HF   64
#define EPSV 1e-5f
#define FULL 0xffffffffu

typedef unsigned long long ull;

// Scratch (device globals; zero-initialized at load, self-cleaned per call)
__device__ __half2  g_thA[(size_t)NN * 32]; // pre-scaled features dinv*t (buf A)
__device__ __half2  g_thB[(size_t)NN * 32]; // pre-scaled features dinv*t (buf B)
__device__ int      g_deg[NN];              // edge-only in-degree (reset by scan1)
__device__ float    g_dinv[NN];             // (deg+1)^{-1/2}
__device__ int      g_rowptr[NN + 1];       // CSR row pointers (by target)
__device__ int      g_cursor[NN];           // fill cursors
__device__ int      g_csr[EE];              // source node per CSR slot
__device__ int      g_bsum[128];            // scan block sums
__device__ float    g_psum[GG * HF];        // pooling: sum   (reset by mlp)
__device__ unsigned g_pmax[GG * HF];        // pooling: max   (reset by mlp)
__device__ int      g_pcnt[GG];             // pooling: count (reset by mlp)

// ---------------------------- f32x2 helpers --------------------------------

__device__ __forceinline__ ull ffma2(ull a, ull b, ull c) {
    ull d;
    asm("fma.rn.f32x2 %0, %1, %2, %3;" : "=l"(d) : "l"(a), "l"(b), "l"(c));
    return d;
}
__device__ __forceinline__ ull pack2(float x, float y) {
    ull d;
    asm("mov.b64 %0, {%1, %2};" : "=l"(d) : "f"(x), "f"(y));
    return d;
}
__device__ __forceinline__ float2 unpack2(ull v) {
    float2 r;
    asm("mov.b64 {%0, %1}, %2;" : "=f"(r.x), "=f"(r.y) : "l"(v));
    return r;
}

// --------------------------- 16-lane gather ---------------------------------
// T viewed as uint2 rows: row i = T[i*16 .. i*16+15] (16 lanes x 8B = 128B).
// Lane (half, fl): accumulates features 4*fl..4*fl+3 of edges in stream
// 'half'. Caller merges halves with shfl_xor(16).
__device__ __forceinline__ void acc_pair(uint2 r, float2& A, float2& B) {
    float2 f0 = __half22float2(*(__half2*)&r.x);
    float2 f1 = __half22float2(*(__half2*)&r.y);
    A.x += f0.x; A.y += f0.y; B.x += f1.x; B.y += f1.y;
}

__device__ __forceinline__ void gather16(const uint2* __restrict__ T,
                                         int i, int half, int fl,
                                         float2& A, float2& B) {
    // self row counted once (half 0 only)
    uint2 s = make_uint2(0u, 0u);
    if (half == 0) s = __ldg(&T[(size_t)i * 16 + fl]);
    A = __half22float2(*(__half2*)&s.x);
    B = __half22float2(*(__half2*)&s.y);

    int k   = __ldg(&g_rowptr[i]);
    int end = __ldg(&g_rowptr[i + 1]);

    // head singles to reach int4 alignment
    while (k < end && (k & 3)) {
        int e = __ldg(&g_csr[k]);
        uint2 r = make_uint2(0u, 0u);
        if (half == 0) r = __ldg(&T[(size_t)e * 16 + fl]);
        acc_pair(r, A, B);
        k++;
    }

    // pipelined 8-edge main loop (2 int4 + 4 two-row LDG.64 in flight)
    if (k + 7 < end) {
        int4 c0 = *(const int4*)&g_csr[k];
        int4 c1 = *(const int4*)&g_csr[k + 4];
        int sA = half ? c0.y : c0.x;
        int sB = half ? c0.w : c0.z;
        int sC = half ? c1.y : c1.x;
        int sD = half ? c1.w : c1.z;
        uint2 rA = __ldg(&T[(size_t)sA * 16 + fl]);
        uint2 rB = __ldg(&T[(size_t)sB * 16 + fl]);
        uint2 rC = __ldg(&T[(size_t)sC * 16 + fl]);
        uint2 rD = __ldg(&T[(size_t)sD * 16 + fl]);
        k += 8;
        while (k + 7 < end) {
            int4 n0 = *(const int4*)&g_csr[k];
            int4 n1 = *(const int4*)&g_csr[k + 4];
            int tA = half ? n0.y : n0.x;
            int tB = half ? n0.w : n0.z;
            int tC = half ? n1.y : n1.x;
            int tD = half ? n1.w : n1.z;
            uint2 qA = __ldg(&T[(size_t)tA * 16 + fl]);
            uint2 qB = __ldg(&T[(size_t)tB * 16 + fl]);
            uint2 qC = __ldg(&T[(size_t)tC * 16 + fl]);
            uint2 qD = __ldg(&T[(size_t)tD * 16 + fl]);
            __half2 m0 = __hadd2(*(__half2*)&rA.x, *(__half2*)&rB.x);
            __half2 m1 = __hadd2(*(__half2*)&rA.y, *(__half2*)&rB.y);
            __half2 m2 = __hadd2(*(__half2*)&rC.x, *(__half2*)&rD.x);
            __half2 m3 = __hadd2(*(__half2*)&rC.y, *(__half2*)&rD.y);
            __half2 p0 = __hadd2(m0, m2);
            __half2 p1 = __hadd2(m1, m3);
            float2 f0 = __half22float2(p0);
            float2 f1 = __half22float2(p1);
            A.x += f0.x; A.y += f0.y; B.x += f1.x; B.y += f1.y;
            rA = qA; rB = qB; rC = qC; rD = qD;
            k += 8;
        }
        // drain
        __half2 m0 = __hadd2(*(__half2*)&rA.x, *(__half2*)&rB.x);
        __half2 m1 = __hadd2(*(__half2*)&rA.y, *(__half2*)&rB.y);
        __half2 m2 = __hadd2(*(__half2*)&rC.x, *(__half2*)&rD.x);
        __half2 m3 = __hadd2(*(__half2*)&rC.y, *(__half2*)&rD.y);
        __half2 p0 = __hadd2(m0, m2);
        __half2 p1 = __hadd2(m1, m3);
        float2 f0 = __half22float2(p0);
        float2 f1 = __half22float2(p1);
        A.x += f0.x; A.y += f0.y; B.x += f1.x; B.y += f1.y;
    }

    // one 4-edge group
    if (k + 3 < end) {
        int4 c0 = *(const int4*)&g_csr[k];
        int sA = half ? c0.y : c0.x;
        int sB = half ? c0.w : c0.z;
        uint2 rA = __ldg(&T[(size_t)sA * 16 + fl]);
        uint2 rB = __ldg(&T[(size_t)sB * 16 + fl]);
        __half2 m0 = __hadd2(*(__half2*)&rA.x, *(__half2*)&rB.x);
        __half2 m1 = __hadd2(*(__half2*)&rA.y, *(__half2*)&rB.y);
        float2 f0 = __half22float2(m0);
        float2 f1 = __half22float2(m1);
        A.x += f0.x; A.y += f0.y; B.x += f1.x; B.y += f1.y;
        k += 4;
    }

    // tail singles
    while (k < end) {
        int e = __ldg(&g_csr[k]);
        uint2 r = make_uint2(0u, 0u);
        if (half == 0) r = __ldg(&T[(size_t)e * 16 + fl]);
        acc_pair(r, A, B);
        k++;
    }
}

__device__ __forceinline__ void merge16(float2& A, float2& B) {
    A.x += __shfl_xor_sync(FULL, A.x, 16);
    A.y += __shfl_xor_sync(FULL, A.y, 16);
    B.x += __shfl_xor_sync(FULL, B.x, 16);
    B.y += __shfl_xor_sync(FULL, B.y, 16);
}

// --------------------------- setup kernels ---------------------------------

__global__ void deg_kernel(const int* __restrict__ ecol) {
    int base = (blockIdx.x * blockDim.x + threadIdx.x) * 4;
    if (base + 3 < EE) {
        int4 c = *(const int4*)(ecol + base);
        atomicAdd(&g_deg[c.x], 1);
        atomicAdd(&g_deg[c.y], 1);
        atomicAdd(&g_deg[c.z], 1);
        atomicAdd(&g_deg[c.w], 1);
    } else {
        for (int e = base; e < EE; e++) atomicAdd(&g_deg[ecol[e]], 1);
    }
}

__global__ void scan1_kernel() {
    __shared__ int sbuf[1024];
    int t = threadIdx.x;
    int idx = blockIdx.x * 1024 + t;
    int v = 0;
    if (idx < NN) {
        v = g_deg[idx];                         // edges only
        g_deg[idx] = 0;                         // self-clean for next call
        g_dinv[idx] = rsqrtf((float)(v + 1));   // +1 self loop
    }
    sbuf[t] = v;
    __syncthreads();
    for (int off = 1; off < 1024; off <<= 1) {
        int tmp = (t >= off) ? sbuf[t - off] : 0;
        __syncthreads();
        sbuf[t] += tmp;
        __syncthreads();
    }
    if (idx < NN) g_rowptr[idx] = sbuf[t] - v;
    if (t == 1023) g_bsum[blockIdx.x] = sbuf[1023];
}

__global__ void scan2_kernel(int nb) {
    __shared__ int sb[128];
    int t = threadIdx.x;
    int v = (t < nb) ? g_bsum[t] : 0;
    sb[t] = v;
    __syncthreads();
    for (int off = 1; off < 128; off <<= 1) {
        int tmp = (t >= off) ? sb[t - off] : 0;
        __syncthreads();
        sb[t] += tmp;
        __syncthreads();
    }
    if (t < nb) g_bsum[t] = sb[t] - v;
}

__global__ void scan3_kernel() {
    int idx = blockIdx.x * blockDim.x + threadIdx.x;
    if (idx < NN) {
        int rp = g_rowptr[idx] + g_bsum[idx >> 10];
        g_rowptr[idx] = rp;
        g_cursor[idx] = rp;
    }
    if (idx == 0) g_rowptr[NN] = EE;
}

__global__ void csr_kernel(const int* __restrict__ erow, const int* __restrict__ ecol) {
    int base = (blockIdx.x * blockDim.x + threadIdx.x) * 4;
    if (base + 3 < EE) {
        int4 r = *(const int4*)(erow + base);
        int4 c = *(const int4*)(ecol + base);
        g_csr[atomicAdd(&g_cursor[c.x], 1)] = r.x;
        g_csr[atomicAdd(&g_cursor[c.y], 1)] = r.y;
        g_csr[atomicAdd(&g_cursor[c.z], 1)] = r.z;
        g_csr[atomicAdd(&g_cursor[c.w], 1)] = r.w;
    } else {
        for (int e = base; e < EE; e++)
            g_csr[atomicAdd(&g_cursor[ecol[e]], 1)] = erow[e];
    }
}

// --------------------------- layer-0 GEMM -----------------------------------
// (Unchanged.) Warp-per-8-nodes, k-split FFMA2; epilogue scales by dinv and
// stores pre-scaled half2 rows into g_thA.
__global__ __launch_bounds__(256) void gemm26_kernel(const float* __restrict__ x,
                                                     const float* __restrict__ W) {
    __shared__ __align__(16) ull  Wp[14 * HF];
    __shared__ __align__(16) float xsf[64 * 28];
    int tid = threadIdx.x;
    for (int i = tid; i < 14 * HF; i += 256) {
        int k2 = i >> 6, c = i & 63;
        float w0 = (2 * k2     < INF) ? W[(2 * k2)     * HF + c] : 0.f;
        float w1 = (2 * k2 + 1 < INF) ? W[(2 * k2 + 1) * HF + c] : 0.f;
        Wp[i] = pack2(w0, w1);
    }
    int base = blockIdx.x * 64;
    int cnt = min(64, NN - base);
    for (int i = tid; i < cnt * 28; i += 256) {
        int row = i / 28, col = i - row * 28;
        xsf[i] = (col < INF) ? __ldg(&x[(size_t)(base + row) * INF + col]) : 0.f;
    }
    __syncthreads();

    int lane = tid & 31;
    int n0 = (tid >> 5) * 8;
    if (n0 >= cnt) return;
    const longlong2* X4 = (const longlong2*)xsf;
    const longlong2* Wq = (const longlong2*)Wp;

    ull a0[8], a1[8];
#pragma unroll
    for (int n = 0; n < 8; n++) { a0[n] = 0ull; a1[n] = 0ull; }
#pragma unroll
    for (int k4 = 0; k4 < 7; k4++) {
        longlong2 wq0 = Wq[(2 * k4) * 32 + lane];
        longlong2 wq1 = Wq[(2 * k4 + 1) * 32 + lane];
#pragma unroll
        for (int n = 0; n < 8; n++) {
            longlong2 xq = X4[(n0 + n) * 7 + k4];
            a0[n] = ffma2((ull)xq.x, (ull)wq0.x, a0[n]);
            a1[n] = ffma2((ull)xq.x, (ull)wq0.y, a1[n]);
            a0[n] = ffma2((ull)xq.y, (ull)wq1.x, a0[n]);
            a1[n] = ffma2((ull)xq.y, (ull)wq1.y, a1[n]);
        }
    }
#pragma unroll
    for (int n = 0; n < 8; n++) {
        int node = base + n0 + n;
        if (node < NN) {
            float dn = __ldg(&g_dinv[node]);
            float2 v0 = unpack2(a0[n]);
            float2 v1 = unpack2(a1[n]);
            g_thA[(size_t)node * 32 + lane] =
                __floats2half2_rn(dn * (v0.x + v0.y), dn * (v1.x + v1.y));
        }
    }
}

// ------------------------ fused aggregate + GEMM -----------------------------
// Block = 64 nodes. Phase 1: warp-per-node 16-lane gather + BN/ReLU -> fp32
// smem tile (half 0 stores float4). Phase 2: FFMA2 gemm (unchanged).
template <int SRCB>
__global__ __launch_bounds__(256) void aggmm_kernel(
        const float* __restrict__ W,
        const float* __restrict__ bias,
        const float* __restrict__ bng, const float* __restrict__ bnb,
        const float* __restrict__ bnm, const float* __restrict__ bnv,
        int layer) {
    const uint2* __restrict__ tin = (const uint2*)(SRCB ? g_thB : g_thA);
    __half2* __restrict__ tout    = SRCB ? g_thA : g_thB;

    __shared__ __align__(16) ull    Wp[32 * HF];   // 16 KB
    __shared__ __align__(16) float4 hs[64 * 16];   // 16 KB fp32 h tile
    int tid = threadIdx.x;
    for (int i = tid; i < 32 * HF; i += 256) {
        int k2 = i >> 6, c = i & 63;
        Wp[i] = pack2(W[(2 * k2) * HF + c], W[(2 * k2 + 1) * HF + c]);
    }
    int base = blockIdx.x * 64;
    int cnt = min(64, NN - base);
    int lane = tid & 31;
    int warp = tid >> 5;
    int half = lane >> 4;
    int fl   = lane & 15;
    int o = layer * HF;
    int cb = 4 * fl;
    float4 g4 = *(const float4*)&bng[o + cb];
    float4 v4 = *(const float4*)&bnv[o + cb];
    float4 m4 = *(const float4*)&bnm[o + cb];
    float4 b4 = *(const float4*)&bnb[o + cb];
    float4 bi = *(const float4*)&bias[cb];
    float sc0 = g4.x * rsqrtf(v4.x + EPSV), sc1 = g4.y * rsqrtf(v4.y + EPSV);
    float sc2 = g4.z * rsqrtf(v4.z + EPSV), sc3 = g4.w * rsqrtf(v4.w + EPSV);
    float sh0 = (bi.x - m4.x) * sc0 + b4.x, sh1 = (bi.y - m4.y) * sc1 + b4.y;
    float sh2 = (bi.z - m4.z) * sc2 + b4.z, sh3 = (bi.w - m4.w) * sc3 + b4.w;

    // Phase 1: aggregate 8 nodes per warp into smem
    int nend = min(warp * 8 + 8, cnt);
    for (int n = warp * 8; n < nend; n++) {
        int i = base + n;
        float di = __ldg(&g_dinv[i]);
        float2 A, B;
        gather16(tin, i, half, fl, A, B);
        merge16(A, B);
        if (half == 0) {
            float h0 = fmaxf(fmaf(A.x, di * sc0, sh0), 0.f);
            float h1 = fmaxf(fmaf(A.y, di * sc1, sh1), 0.f);
            float h2 = fmaxf(fmaf(B.x, di * sc2, sh2), 0.f);
            float h3 = fmaxf(fmaf(B.y, di * sc3, sh3), 0.f);
            hs[n * 16 + fl] = make_float4(h0, h1, h2, h3);
        }
    }
    __syncthreads();

    // Phase 2: gemm from smem tile (unchanged core)
    int n0 = warp * 8;
    if (n0 >= cnt) return;
    const longlong2* X4 = (const longlong2*)hs;
    const longlong2* Wq = (const longlong2*)Wp;
    ull a0[8], a1[8];
#pragma unroll
    for (int n = 0; n < 8; n++) { a0[n] = 0ull; a1[n] = 0ull; }
#pragma unroll
    for (int k4 = 0; k4 < 16; k4++) {
        longlong2 wq0 = Wq[(2 * k4) * 32 + lane];
        longlong2 wq1 = Wq[(2 * k4 + 1) * 32 + lane];
#pragma unroll
        for (int n = 0; n < 8; n++) {
            longlong2 xq = X4[(n0 + n) * 16 + k4];
            a0[n] = ffma2((ull)xq.x, (ull)wq0.x, a0[n]);
            a1[n] = ffma2((ull)xq.x, (ull)wq0.y, a1[n]);
            a0[n] = ffma2((ull)xq.y, (ull)wq1.x, a0[n]);
            a1[n] = ffma2((ull)xq.y, (ull)wq1.y, a1[n]);
        }
    }
#pragma unroll
    for (int n = 0; n < 8; n++) {
        int node = base + n0 + n;
        if (node < NN) {
            float dn = __ldg(&g_dinv[node]);
            float2 v0 = unpack2(a0[n]);
            float2 v1 = unpack2(a1[n]);
            tout[(size_t)node * 32 + lane] =
                __floats2half2_rn(dn * (v0.x + v0.y), dn * (v1.x + v1.y));
        }
    }
}

// ------------------------ final aggregate + pooling ---------------------------
__global__ __launch_bounds__(256) void aggpool_kernel(
        const float* __restrict__ bias,
        const float* __restrict__ bng, const float* __restrict__ bnb,
        const float* __restrict__ bnm, const float* __restrict__ bnv,
        int layer, const int* __restrict__ batch) {
    int lane = threadIdx.x & 31;
    int warp = (blockIdx.x * blockDim.x + threadIdx.x) >> 5;
    int nw   = (gridDim.x * blockDim.x) >> 5;
    int half = lane >> 4;
    int fl   = lane & 15;
    int o = layer * HF;
    int cb = 4 * fl;
    float4 g4 = *(const float4*)&bng[o + cb];
    float4 v4 = *(const float4*)&bnv[o + cb];
    float4 m4 = *(const float4*)&bnm[o + cb];
    float4 b4 = *(const float4*)&bnb[o + cb];
    float4 bi = *(const float4*)&bias[cb];
    float sc0 = g4.x * rsqrtf(v4.x + EPSV), sc1 = g4.y * rsqrtf(v4.y + EPSV);
    float sc2 = g4.z * rsqrtf(v4.z + EPSV), sc3 = g4.w * rsqrtf(v4.w + EPSV);
    float sh0 = (bi.x - m4.x) * sc0 + b4.x, sh1 = (bi.y - m4.y) * sc1 + b4.y;
    float sh2 = (bi.z - m4.z) * sc2 + b4.z, sh3 = (bi.w - m4.w) * sc3 + b4.w;

    const uint2* T = (const uint2*)g_thA;
    for (int i = warp; i < NN; i += nw) {
        float di = __ldg(&g_dinv[i]);
        float2 A, B;
        gather16(T, i, half, fl, A, B);
        merge16(A, B);
        if (half == 0) {
            float h0 = fmaxf(fmaf(A.x, di * sc0, sh0), 0.f);
            float h1 = fmaxf(fmaf(A.y, di * sc1, sh1), 0.f);
            float h2 = fmaxf(fmaf(B.x, di * sc2, sh2), 0.f);
            float h3 = fmaxf(fmaf(B.y, di * sc3, sh3), 0.f);
            int g = __ldg(&batch[i]);
            atomicAdd(&g_psum[g * HF + cb],     h0);
            atomicAdd(&g_psum[g * HF + cb + 1], h1);
            atomicAdd(&g_psum[g * HF + cb + 2], h2);
            atomicAdd(&g_psum[g * HF + cb + 3], h3);
            atomicMax(&g_pmax[g * HF + cb],     __float_as_uint(h0));
            atomicMax(&g_pmax[g * HF + cb + 1], __float_as_uint(h1));
            atomicMax(&g_pmax[g * HF + cb + 2], __float_as_uint(h2));
            atomicMax(&g_pmax[g * HF + cb + 3], __float_as_uint(h3));
            if (fl == 0) atomicAdd(&g_pcnt[g], 1);
        }
    }
}

// ------------------------------ head -----------------------------------------

__global__ void mlp_kernel(const float* __restrict__ Wc1, const float* __restrict__ bc1,
                           const float* __restrict__ Wc2, const float* __restrict__ bc2,
                           float* __restrict__ out) {
    int lane = threadIdx.x & 31;
    int g = (blockIdx.x * blockDim.x + threadIdx.x) >> 5;
    if (g >= GG) return;
    float inv = 1.0f / fmaxf((float)g_pcnt[g], 1.0f);
    float p0 = g_psum[g * HF + lane]      * inv;
    float p1 = g_psum[g * HF + lane + 32] * inv;
    float p2 = __uint_as_float(g_pmax[g * HF + lane]);
    float p3 = __uint_as_float(g_pmax[g * HF + lane + 32]);
    g_psum[g * HF + lane] = 0.f;  g_psum[g * HF + lane + 32] = 0.f;
    g_pmax[g * HF + lane] = 0u;   g_pmax[g * HF + lane + 32] = 0u;
    if (lane == 0) g_pcnt[g] = 0;

    float h0 = bc1[lane], h1 = bc1[lane + 32];
#pragma unroll
    for (int k = 0; k < 32; k++) {
        float v0 = __shfl_sync(FULL, p0, k);
        float v1 = __shfl_sync(FULL, p1, k);
        float v2 = __shfl_sync(FULL, p2, k);
        float v3 = __shfl_sync(FULL, p3, k);
        h0 = fmaf(v0, Wc1[k * HF + lane], h0);
        h0 = fmaf(v1, Wc1[(k + 32) * HF + lane], h0);
        h0 = fmaf(v2, Wc1[(k + 64) * HF + lane], h0);
        h0 = fmaf(v3, Wc1[(k + 96) * HF + lane], h0);
        h1 = fmaf(v0, Wc1[k * HF + lane + 32], h1);
        h1 = fmaf(v1, Wc1[(k + 32) * HF + lane + 32], h1);
        h1 = fmaf(v2, Wc1[(k + 64) * HF + lane + 32], h1);
        h1 = fmaf(v3, Wc1[(k + 96) * HF + lane + 32], h1);
    }
    h0 = fmaxf(h0, 0.f);
    h1 = fmaxf(h1, 0.f);
    float o0 = h0 * Wc2[lane * 2 + 0] + h1 * Wc2[(lane + 32) * 2 + 0];
    float o1 = h0 * Wc2[lane * 2 + 1] + h1 * Wc2[(lane + 32) * 2 + 1];
#pragma unroll
    for (int off = 16; off; off >>= 1) {
        o0 += __shfl_down_sync(FULL, o0, off);
        o1 += __shfl_down_sync(FULL, o1, off);
    }
    if (lane == 0) {
        out[g * 2 + 0] = o0 + bc2[0];
        out[g * 2 + 1] = o1 + bc2[1];
    }
}

// ------------------------------ launch ---------------------------------------

extern "C" void kernel_launch(void* const* d_in, const int* in_sizes, int n_in,
                              void* d_out, int out_size) {
    const float* x    = (const float*)d_in[0];
    const int*   erow = (const int*)d_in[1];
    const int*   ecol = (const int*)d_in[2];
    const int*   batch= (const int*)d_in[3];
    const float* W0   = (const float*)d_in[4];
    const float* b0   = (const float*)d_in[5];
    const float* W1   = (const float*)d_in[6];
    const float* b1   = (const float*)d_in[7];
    const float* W2   = (const float*)d_in[8];
    const float* b2   = (const float*)d_in[9];
    const float* bng  = (const float*)d_in[10];
    const float* bnb  = (const float*)d_in[11];
    const float* bnm  = (const float*)d_in[12];
    const float* bnv  = (const float*)d_in[13];
    const float* Wc1  = (const float*)d_in[14];
    const float* bc1  = (const float*)d_in[15];
    const float* Wc2  = (const float*)d_in[16];
    const float* bc2  = (const float*)d_in[17];
    float* out = (float*)d_out;

    const int GB = 2048, BT = 256;
    const int TILE_BLOCKS = (NN + 63) / 64;

    deg_kernel<<<(EE / 4 + 255) / 256, 256>>>(ecol);
    scan1_kernel<<<(NN + 1023) / 1024, 1024>>>();        // computes g_dinv
    scan2_kernel<<<1, 128>>>((NN + 1023) / 1024);
    gemm26_kernel<<<TILE_BLOCKS, 256>>>(x, W0);          // x,W0 -> thA
    scan3_kernel<<<(NN + 255) / 256, 256>>>();
    csr_kernel<<<(EE / 4 + 255) / 256, 256>>>(erow, ecol);

    // fused layers: agg(l) + gemm(W_{l+1})   (thA -> thB -> thA)
    aggmm_kernel<0><<<TILE_BLOCKS, 256>>>(W1, b0, bng, bnb, bnm, bnv, 0);
    aggmm_kernel<1><<<TILE_BLOCKS, 256>>>(W2, b1, bng, bnb, bnm, bnv, 1);
    // final layer: aggregate + pooling only (reads thA)
    aggpool_kernel<<<GB, BT>>>(b2, bng, bnb, bnm, bnv, 2, batch);
    mlp_kernel<<<(GG * 32 + 255) / 256, 256>>>(Wc1, bc1, Wc2, bc2, out);
}

// round 17
// speedup vs baseline: 1.0969x; 1.0969x over previous
#include <cuda_runtime.h>
#include <cuda_fp16.h>

// ---------------------------------------------------------------------------
// GCN: 3x (GEMM -> GCN-normalized aggregate w/ self loops -> BN(eval)+ReLU)
//      -> global mean+max pool per graph -> 2-layer MLP head.
// R14 skeleton (258.5us, best). Single change this round: csr metadata read
// as ONE uniform int4 per 4 edges (g_csr 16B-aligned; scalar head/tail for
// unaligned row starts). Row-load path identical to R14: 4 independent
// warp-wide fp16 row streams, 4-ahead prefetch, fp32 accumulation.
// ---------------------------------------------------------------------------

#define NN   100000
#define EE   1600000
#define GG   512
#define INF  26
#define HF   64
#define EPSV 1e-5f
#define FULL 0xffffffffu

typedef unsigned long long ull;

// Scratch (device globals; zero-initialized at load, self-cleaned per call)
__device__ __half2  g_thA[(size_t)NN * 32]; // pre-scaled features dinv*t (buf A)
__device__ __half2  g_thB[(size_t)NN * 32]; // pre-scaled features dinv*t (buf B)
__device__ int      g_deg[NN];              // edge-only in-degree (reset by scan1)
__device__ float    g_dinv[NN];             // (deg+1)^{-1/2}
__device__ int      g_rowptr[NN + 1];       // CSR row pointers (by target)
__device__ int      g_cursor[NN];           // fill cursors
__device__ __align__(16) int g_csr[EE];     // source node per CSR slot
__device__ int      g_bsum[128];            // scan block sums
__device__ float    g_psum[GG * HF];        // pooling: sum   (reset by mlp)
__device__ unsigned g_pmax[GG * HF];        // pooling: max   (reset by mlp)
__device__ int      g_pcnt[GG];             // pooling: count (reset by mlp)

// ---------------------------- f32x2 helpers --------------------------------

__device__ __forceinline__ ull ffma2(ull a, ull b, ull c) {
    ull d;
    asm("fma.rn.f32x2 %0, %1, %2, %3;" : "=l"(d) : "l"(a), "l"(b), "l"(c));
    return d;
}
__device__ __forceinline__ ull pack2(float x, float y) {
    ull d;
    asm("mov.b64 %0, {%1, %2};" : "=l"(d) : "f"(x), "f"(y));
    return d;
}
__device__ __forceinline__ float2 unpack2(ull v) {
    float2 r;
    asm("mov.b64 {%0, %1}, %2;" : "=f"(r.x), "=f"(r.y) : "l"(v));
    return r;
}

// Unweighted gather-sum over pre-scaled fp16 rows (self row + in-edges).
// 4 independent row streams, metadata via uniform int4 (4 edges/load),
// prefetched one int4-group ahead. fp32 accumulation.
__device__ __forceinline__ float2 gather_sum(const __half2* __restrict__ T,
                                             int i, int lane) {
    float2 accA = __half22float2(__ldg(&T[(size_t)i * 32 + lane]));  // self
    float2 accB = make_float2(0.f, 0.f);
    float2 accC = make_float2(0.f, 0.f);
    float2 accD = make_float2(0.f, 0.f);
    int k   = __ldg(&g_rowptr[i]);
    int end = __ldg(&g_rowptr[i + 1]);

    // head singles until k is 4-aligned
    while (k < end && (k & 3)) {
        int s = __ldg(&g_csr[k]);
        float2 f = __half22float2(__ldg(&T[(size_t)s * 32 + lane]));
        accA.x += f.x; accA.y += f.y;
        k++;
    }

    // pipelined 4-edge groups (1 uniform int4 + 4 row LDG.32 per group)
    if (k + 3 < end) {
        int4 c = *(const int4*)&g_csr[k];
        __half2 r0 = __ldg(&T[(size_t)c.x * 32 + lane]);
        __half2 r1 = __ldg(&T[(size_t)c.y * 32 + lane]);
        __half2 r2 = __ldg(&T[(size_t)c.z * 32 + lane]);
        __half2 r3 = __ldg(&T[(size_t)c.w * 32 + lane]);
        k += 4;
        while (k + 3 < end) {
            int4 n = *(const int4*)&g_csr[k];
            __half2 q0 = __ldg(&T[(size_t)n.x * 32 + lane]);
            __half2 q1 = __ldg(&T[(size_t)n.y * 32 + lane]);
            __half2 q2 = __ldg(&T[(size_t)n.z * 32 + lane]);
            __half2 q3 = __ldg(&T[(size_t)n.w * 32 + lane]);
            float2 f0 = __half22float2(r0);
            float2 f1 = __half22float2(r1);
            float2 f2 = __half22float2(r2);
            float2 f3 = __half22float2(r3);
            accA.x += f0.x; accA.y += f0.y;
            accB.x += f1.x; accB.y += f1.y;
            accC.x += f2.x; accC.y += f2.y;
            accD.x += f3.x; accD.y += f3.y;
            r0 = q0; r1 = q1; r2 = q2; r3 = q3;
            k += 4;
        }
        float2 f0 = __half22float2(r0);
        float2 f1 = __half22float2(r1);
        float2 f2 = __half22float2(r2);
        float2 f3 = __half22float2(r3);
        accA.x += f0.x; accA.y += f0.y;
        accB.x += f1.x; accB.y += f1.y;
        accC.x += f2.x; accC.y += f2.y;
        accD.x += f3.x; accD.y += f3.y;
    }

    // tail singles (<=3 edges)
    for (; k < end; k++) {
        int s = __ldg(&g_csr[k]);
        float2 f = __half22float2(__ldg(&T[(size_t)s * 32 + lane]));
        accA.x += f.x; accA.y += f.y;
    }
    return make_float2((accA.x + accB.x) + (accC.x + accD.x),
                       (accA.y + accB.y) + (accC.y + accD.y));
}

// --------------------------- setup kernels ---------------------------------

__global__ void deg_kernel(const int* __restrict__ ecol) {
    int base = (blockIdx.x * blockDim.x + threadIdx.x) * 4;
    if (base + 3 < EE) {
        int4 c = *(const int4*)(ecol + base);
        atomicAdd(&g_deg[c.x], 1);
        atomicAdd(&g_deg[c.y], 1);
        atomicAdd(&g_deg[c.z], 1);
        atomicAdd(&g_deg[c.w], 1);
    } else {
        for (int e = base; e < EE; e++) atomicAdd(&g_deg[ecol[e]], 1);
    }
}

__global__ void scan1_kernel() {
    __shared__ int sbuf[1024];
    int t = threadIdx.x;
    int idx = blockIdx.x * 1024 + t;
    int v = 0;
    if (idx < NN) {
        v = g_deg[idx];                         // edges only
        g_deg[idx] = 0;                         // self-clean for next call
        g_dinv[idx] = rsqrtf((float)(v + 1));   // +1 self loop
    }
    sbuf[t] = v;
    __syncthreads();
    for (int off = 1; off < 1024; off <<= 1) {
        int tmp = (t >= off) ? sbuf[t - off] : 0;
        __syncthreads();
        sbuf[t] += tmp;
        __syncthreads();
    }
    if (idx < NN) g_rowptr[idx] = sbuf[t] - v;
    if (t == 1023) g_bsum[blockIdx.x] = sbuf[1023];
}

__global__ void scan2_kernel(int nb) {
    __shared__ int sb[128];
    int t = threadIdx.x;
    int v = (t < nb) ? g_bsum[t] : 0;
    sb[t] = v;
    __syncthreads();
    for (int off = 1; off < 128; off <<= 1) {
        int tmp = (t >= off) ? sb[t - off] : 0;
        __syncthreads();
        sb[t] += tmp;
        __syncthreads();
    }
    if (t < nb) g_bsum[t] = sb[t] - v;
}

__global__ void scan3_kernel() {
    int idx = blockIdx.x * blockDim.x + threadIdx.x;
    if (idx < NN) {
        int rp = g_rowptr[idx] + g_bsum[idx >> 10];
        g_rowptr[idx] = rp;
        g_cursor[idx] = rp;
    }
    if (idx == 0) g_rowptr[NN] = EE;
}

__global__ void csr_kernel(const int* __restrict__ erow, const int* __restrict__ ecol) {
    int base = (blockIdx.x * blockDim.x + threadIdx.x) * 4;
    if (base + 3 < EE) {
        int4 r = *(const int4*)(erow + base);
        int4 c = *(const int4*)(ecol + base);
        g_csr[atomicAdd(&g_cursor[c.x], 1)] = r.x;
        g_csr[atomicAdd(&g_cursor[c.y], 1)] = r.y;
        g_csr[atomicAdd(&g_cursor[c.z], 1)] = r.z;
        g_csr[atomicAdd(&g_cursor[c.w], 1)] = r.w;
    } else {
        for (int e = base; e < EE; e++)
            g_csr[atomicAdd(&g_cursor[ecol[e]], 1)] = erow[e];
    }
}

// --------------------------- layer-0 GEMM -----------------------------------
// (Unchanged.) Warp-per-8-nodes, k-split FFMA2; epilogue scales by dinv and
// stores pre-scaled half2 rows into g_thA.
__global__ __launch_bounds__(256) void gemm26_kernel(const float* __restrict__ x,
                                                     const float* __restrict__ W) {
    __shared__ __align__(16) ull  Wp[14 * HF];
    __shared__ __align__(16) float xsf[64 * 28];
    int tid = threadIdx.x;
    for (int i = tid; i < 14 * HF; i += 256) {
        int k2 = i >> 6, c = i & 63;
        float w0 = (2 * k2     < INF) ? W[(2 * k2)     * HF + c] : 0.f;
        float w1 = (2 * k2 + 1 < INF) ? W[(2 * k2 + 1) * HF + c] : 0.f;
        Wp[i] = pack2(w0, w1);
    }
    int base = blockIdx.x * 64;
    int cnt = min(64, NN - base);
    for (int i = tid; i < cnt * 28; i += 256) {
        int row = i / 28, col = i - row * 28;
        xsf[i] = (col < INF) ? __ldg(&x[(size_t)(base + row) * INF + col]) : 0.f;
    }
    __syncthreads();

    int lane = tid & 31;
    int n0 = (tid >> 5) * 8;
    if (n0 >= cnt) return;
    const longlong2* X4 = (const longlong2*)xsf;
    const longlong2* Wq = (const longlong2*)Wp;

    ull a0[8], a1[8];
#pragma unroll
    for (int n = 0; n < 8; n++) { a0[n] = 0ull; a1[n] = 0ull; }
#pragma unroll
    for (int k4 = 0; k4 < 7; k4++) {
        longlong2 wq0 = Wq[(2 * k4) * 32 + lane];
        longlong2 wq1 = Wq[(2 * k4 + 1) * 32 + lane];
#pragma unroll
        for (int n = 0; n < 8; n++) {
            longlong2 xq = X4[(n0 + n) * 7 + k4];
            a0[n] = ffma2((ull)xq.x, (ull)wq0.x, a0[n]);
            a1[n] = ffma2((ull)xq.x, (ull)wq0.y, a1[n]);
            a0[n] = ffma2((ull)xq.y, (ull)wq1.x, a0[n]);
            a1[n] = ffma2((ull)xq.y, (ull)wq1.y, a1[n]);
        }
    }
#pragma unroll
    for (int n = 0; n < 8; n++) {
        int node = base + n0 + n;
        if (node < NN) {
            float dn = __ldg(&g_dinv[node]);
            float2 v0 = unpack2(a0[n]);
            float2 v1 = unpack2(a1[n]);
            g_thA[(size_t)node * 32 + lane] =
                __floats2half2_rn(dn * (v0.x + v0.y), dn * (v1.x + v1.y));
        }
    }
}

// ------------------------ fused aggregate + GEMM -----------------------------
// Block = 64 nodes. Phase 1: warp-per-node gather from tin + BN/ReLU ->
// fp32 smem tile. Phase 2: FFMA2 gemm with W (next layer) from smem;
// epilogue writes pre-scaled fp16 rows to tout.
// SRCB=0: tin=g_thA, tout=g_thB.  SRCB=1: tin=g_thB, tout=g_thA.
template <int SRCB>
__global__ __launch_bounds__(256) void aggmm_kernel(
        const float* __restrict__ W,        // next-layer weight [64,64]
        const float* __restrict__ bias,     // this layer bias
        const float* __restrict__ bng, const float* __restrict__ bnb,
        const float* __restrict__ bnm, const float* __restrict__ bnv,
        int layer) {
    const __half2* __restrict__ tin = SRCB ? g_thB : g_thA;
    __half2* __restrict__ tout      = SRCB ? g_thA : g_thB;

    __shared__ __align__(16) ull    Wp[32 * HF];   // 16 KB
    __shared__ __align__(16) float2 hs[64 * 32];   // 16 KB fp32 h tile
    int tid = threadIdx.x;
    for (int i = tid; i < 32 * HF; i += 256) {
        int k2 = i >> 6, c = i & 63;
        Wp[i] = pack2(W[(2 * k2) * HF + c], W[(2 * k2 + 1) * HF + c]);
    }
    int base = blockIdx.x * 64;
    int cnt = min(64, NN - base);
    int lane = tid & 31;
    int warp = tid >> 5;
    int c0 = 2 * lane, c1 = c0 + 1;
    int o = layer * HF;
    float sc0 = bng[o + c0] * rsqrtf(bnv[o + c0] + EPSV);
    float sc1 = bng[o + c1] * rsqrtf(bnv[o + c1] + EPSV);
    float sh0 = (bias[c0] - bnm[o + c0]) * sc0 + bnb[o + c0];
    float sh1 = (bias[c1] - bnm[o + c1]) * sc1 + bnb[o + c1];

    // Phase 1: aggregate 8 nodes per warp into smem
    int nend = min(warp * 8 + 8, cnt);
    for (int n = warp * 8; n < nend; n++) {
        int i = base + n;
        float di = __ldg(&g_dinv[i]);
        float2 a = gather_sum(tin, i, lane);
        float o0 = fmaxf(fmaf(a.x, di * sc0, sh0), 0.f);
        float o1 = fmaxf(fmaf(a.y, di * sc1, sh1), 0.f);
        hs[n * 32 + lane] = make_float2(o0, o1);
    }
    __syncthreads();

    // Phase 2: gemm from smem tile
    int n0 = warp * 8;
    if (n0 >= cnt) return;
    const longlong2* X4 = (const longlong2*)hs;
    const longlong2* Wq = (const longlong2*)Wp;
    ull a0[8], a1[8];
#pragma unroll
    for (int n = 0; n < 8; n++) { a0[n] = 0ull; a1[n] = 0ull; }
#pragma unroll
    for (int k4 = 0; k4 < 16; k4++) {
        longlong2 wq0 = Wq[(2 * k4) * 32 + lane];
        longlong2 wq1 = Wq[(2 * k4 + 1) * 32 + lane];
#pragma unroll
        for (int n = 0; n < 8; n++) {
            longlong2 xq = X4[(n0 + n) * 16 + k4];
            a0[n] = ffma2((ull)xq.x, (ull)wq0.x, a0[n]);
            a1[n] = ffma2((ull)xq.x, (ull)wq0.y, a1[n]);
            a0[n] = ffma2((ull)xq.y, (ull)wq1.x, a0[n]);
            a1[n] = ffma2((ull)xq.y, (ull)wq1.y, a1[n]);
        }
    }
#pragma unroll
    for (int n = 0; n < 8; n++) {
        int node = base + n0 + n;
        if (node < NN) {
            float dn = __ldg(&g_dinv[node]);
            float2 v0 = unpack2(a0[n]);
            float2 v1 = unpack2(a1[n]);
            tout[(size_t)node * 32 + lane] =
                __floats2half2_rn(dn * (v0.x + v0.y), dn * (v1.x + v1.y));
        }
    }
}

// ------------------------ final aggregate + pooling ---------------------------
// Warp per node (grid-strided); gathers from g_thA, BN/ReLU, pooling only.
__global__ __launch_bounds__(256) void aggpool_kernel(
        const float* __restrict__ bias,
        const float* __restrict__ bng, const float* __restrict__ bnb,
        const float* __restrict__ bnm, const float* __restrict__ bnv,
        int layer, const int* __restrict__ batch) {
    int lane = threadIdx.x & 31;
    int warp = (blockIdx.x * blockDim.x + threadIdx.x) >> 5;
    int nw   = (gridDim.x * blockDim.x) >> 5;
    int c0 = 2 * lane, c1 = c0 + 1;
    int o = layer * HF;
    float sc0 = bng[o + c0] * rsqrtf(bnv[o + c0] + EPSV);
    float sc1 = bng[o + c1] * rsqrtf(bnv[o + c1] + EPSV);
    float sh0 = (bias[c0] - bnm[o + c0]) * sc0 + bnb[o + c0];
    float sh1 = (bias[c1] - bnm[o + c1]) * sc1 + bnb[o + c1];

    for (int i = warp; i < NN; i += nw) {
        float di = __ldg(&g_dinv[i]);
        float2 a = gather_sum(g_thA, i, lane);
        float o0 = fmaxf(fmaf(a.x, di * sc0, sh0), 0.f);
        float o1 = fmaxf(fmaf(a.y, di * sc1, sh1), 0.f);
        int g = __ldg(&batch[i]);
        atomicAdd(&g_psum[g * HF + c0], o0);
        atomicAdd(&g_psum[g * HF + c1], o1);
        atomicMax(&g_pmax[g * HF + c0], __float_as_uint(o0));
        atomicMax(&g_pmax[g * HF + c1], __float_as_uint(o1));
        if (lane == 0) atomicAdd(&g_pcnt[g], 1);
    }
}

// ------------------------------ head -----------------------------------------

__global__ void mlp_kernel(const float* __restrict__ Wc1, const float* __restrict__ bc1,
                           const float* __restrict__ Wc2, const float* __restrict__ bc2,
                           float* __restrict__ out) {
    int lane = threadIdx.x & 31;
    int g = (blockIdx.x * blockDim.x + threadIdx.x) >> 5;
    if (g >= GG) return;
    float inv = 1.0f / fmaxf((float)g_pcnt[g], 1.0f);
    float p0 = g_psum[g * HF + lane]      * inv;
    float p1 = g_psum[g * HF + lane + 32] * inv;
    float p2 = __uint_as_float(g_pmax[g * HF + lane]);
    float p3 = __uint_as_float(g_pmax[g * HF + lane + 32]);
    g_psum[g * HF + lane] = 0.f;  g_psum[g * HF + lane + 32] = 0.f;
    g_pmax[g * HF + lane] = 0u;   g_pmax[g * HF + lane + 32] = 0u;
    if (lane == 0) g_pcnt[g] = 0;

    float h0 = bc1[lane], h1 = bc1[lane + 32];
#pragma unroll
    for (int k = 0; k < 32; k++) {
        float v0 = __shfl_sync(FULL, p0, k);
        float v1 = __shfl_sync(FULL, p1, k);
        float v2 = __shfl_sync(FULL, p2, k);
        float v3 = __shfl_sync(FULL, p3, k);
        h0 = fmaf(v0, Wc1[k * HF + lane], h0);
        h0 = fmaf(v1, Wc1[(k + 32) * HF + lane], h0);
        h0 = fmaf(v2, Wc1[(k + 64) * HF + lane], h0);
        h0 = fmaf(v3, Wc1[(k + 96) * HF + lane], h0);
        h1 = fmaf(v0, Wc1[k * HF + lane + 32], h1);
        h1 = fmaf(v1, Wc1[(k + 32) * HF + lane + 32], h1);
        h1 = fmaf(v2, Wc1[(k + 64) * HF + lane + 32], h1);
        h1 = fmaf(v3, Wc1[(k + 96) * HF + lane + 32], h1);
    }
    h0 = fmaxf(h0, 0.f);
    h1 = fmaxf(h1, 0.f);
    float o0 = h0 * Wc2[lane * 2 + 0] + h1 * Wc2[(lane + 32) * 2 + 0];
    float o1 = h0 * Wc2[lane * 2 + 1] + h1 * Wc2[(lane + 32) * 2 + 1];
#pragma unroll
    for (int off = 16; off; off >>= 1) {
        o0 += __shfl_down_sync(FULL, o0, off);
        o1 += __shfl_down_sync(FULL, o1, off);
    }
    if (lane == 0) {
        out[g * 2 + 0] = o0 + bc2[0];
        out[g * 2 + 1] = o1 + bc2[1];
    }
}

// ------------------------------ launch ---------------------------------------

extern "C" void kernel_launch(void* const* d_in, const int* in_sizes, int n_in,
                              void* d_out, int out_size) {
    const float* x    = (const float*)d_in[0];
    const int*   erow = (const int*)d_in[1];
    const int*   ecol = (const int*)d_in[2];
    const int*   batch= (const int*)d_in[3];
    const float* W0   = (const float*)d_in[4];
    const float* b0   = (const float*)d_in[5];
    const float* W1   = (const float*)d_in[6];
    const float* b1   = (const float*)d_in[7];
    const float* W2   = (const float*)d_in[8];
    const float* b2   = (const float*)d_in[9];
    const float* bng  = (const float*)d_in[10];
    const float* bnb  = (const float*)d_in[11];
    const float* bnm  = (const float*)d_in[12];
    const float* bnv  = (const float*)d_in[13];
    const float* Wc1  = (const float*)d_in[14];
    const float* bc1  = (const float*)d_in[15];
    const float* Wc2  = (const float*)d_in[16];
    const float* bc2  = (const float*)d_in[17];
    float* out = (float*)d_out;

    const int GB = 2048, BT = 256;
    const int TILE_BLOCKS = (NN + 63) / 64;

    deg_kernel<<<(EE / 4 + 255) / 256, 256>>>(ecol);
    scan1_kernel<<<(NN + 1023) / 1024, 1024>>>();        // computes g_dinv
    scan2_kernel<<<1, 128>>>((NN + 1023) / 1024);
    gemm26_kernel<<<TILE_BLOCKS, 256>>>(x, W0);          // x,W0 -> thA
    scan3_kernel<<<(NN + 255) / 256, 256>>>();
    csr_kernel<<<(EE / 4 + 255) / 256, 256>>>(erow, ecol);

    // fused layers: agg(l) + gemm(W_{l+1})   (thA -> thB -> thA)
    aggmm_kernel<0><<<TILE_BLOCKS, 256>>>(W1, b0, bng, bnb, bnm, bnv, 0);
    aggmm_kernel<1><<<TILE_BLOCKS, 256>>>(W2, b1, bng, bnb, bnm, bnv, 1);
    // final layer: aggregate + pooling only (reads thA)
    aggpool_kernel<<<GB, BT>>>(b2, bng, bnb, bnm, bnv, 2, batch);
    mlp_kernel<<<(GG * 32 + 255) / 256, 256>>>(Wc1, bc1, Wc2, bc2, out);
}